// round 13
// baseline (speedup 1.0000x reference)
#include <cuda_runtime.h>
#include <cuda_bf16.h>
#include <stdint.h>

#define BZ 4
#define LL 1024
#define SS 8
#define KH 128
#define EE 512
#define PRIME 2147483647u
#define EMPTYV 0xffffffffu
#define EVCAP 256
#define TBL 4096
#define TMASK 4095
#define MAXOVF 1024

// ---------------- device scratch ----------------
__device__ __align__(16) unsigned int  g_sigT[2 * BZ * KH * LL];   // [z][k][l]
__device__ float         g_lut[129];
__device__ int           g_is64;
__device__ __align__(16) float         g_Mpart[4 * EE * EE];
__device__ __align__(16) float         g_M[EE * EE];        // M2 [e2][e1] fp32
__device__ __align__(16) float         g_u[BZ * LL * EE];   // u fp32 [b][r][e2]
__device__ __align__(16) float         g_vsumP[16 * BZ * EE];
__device__ __align__(16) float         g_vsum[BZ * EE];
__device__ __align__(16) float         g_usum[BZ * EE];
__device__ __align__(16) float         g_cvec[EE];
__device__ float         g_rowinv[BZ * LL];
__device__ int           g_evc[BZ * LL];
__device__ __align__(16) int           g_evj[BZ * LL * EVCAP];
__device__ int           g_nzc[BZ * LL];
__device__ __align__(16) int           g_nzi[BZ * LL * EVCAP];
__device__ __align__(16) float         g_nzw[BZ * LL * EVCAP];

// ---------------- static streams/events (created at program load, before
// the harness's memory checkpoints and before graph capture) ----------------
struct HxStreams {
    cudaStream_t s1, s2;
    cudaEvent_t  e0, e1, e2;
    HxStreams() {
        cudaStreamCreateWithFlags(&s1, cudaStreamNonBlocking);
        cudaStreamCreateWithFlags(&s2, cudaStreamNonBlocking);
        cudaEventCreateWithFlags(&e0, cudaEventDisableTiming);
        cudaEventCreateWithFlags(&e1, cudaEventDisableTiming);
        cudaEventCreateWithFlags(&e2, cudaEventDisableTiming);
    }
};
static HxStreams HX;

// ---------------- f32x2 helpers ----------------
__device__ __forceinline__ unsigned long long pk_dup(float x) {
    unsigned long long d;
    unsigned u = __float_as_uint(x);
    asm("mov.b64 %0, {%1, %1};" : "=l"(d) : "r"(u));
    return d;
}
__device__ __forceinline__ unsigned long long pk_ab(float x, float y) {
    unsigned long long d;
    asm("mov.b64 %0, {%1, %2};" : "=l"(d) : "r"(__float_as_uint(x)), "r"(__float_as_uint(y)));
    return d;
}
__device__ __forceinline__ void ffma2(unsigned long long& d, unsigned long long a,
                                      unsigned long long b) {
    asm("fma.rn.f32x2 %0, %1, %2, %0;" : "+l"(d) : "l"(a), "l"(b));
}
__device__ __forceinline__ float2 up2(unsigned long long d) {
    unsigned lo, hi;
    asm("mov.b64 {%0, %1}, %2;" : "=r"(lo), "=r"(hi) : "l"(d));
    return make_float2(__uint_as_float(lo), __uint_as_float(hi));
}

// ---------------- init: dtype detect + LUT + zero evc + cvec ----------------
__global__ __launch_bounds__(256) void init_kernel(const void* ha,
                                                   const float* __restrict__ Wo,
                                                   const float* __restrict__ bv,
                                                   const float* __restrict__ bo) {
    int bid = blockIdx.x;
    if (bid == 0) {
        int t = threadIdx.x;
        if (t == 0) {
            const int* p = (const int*)ha;
            int is64 = 1;
            for (int i = 0; i < 16; i++)
                if (p[2 * i + 1] != 0) is64 = 0;
            g_is64 = is64;
        }
        if (t < 129) {
            float j = (float)t / 128.0f;
            float delta = 16.0f * (1.0f - j) / (1.0f + j);
            float s = expf(-0.3f * delta);
            g_lut[t] = expf(s);
        }
        return;
    }
    if (bid <= 16) {
        g_evc[(bid - 1) * 256 + threadIdx.x] = 0;
        return;
    }
    int e2 = (bid - 17) * 8 + (threadIdx.x >> 5);
    int lane = threadIdx.x & 31;
    const float* wr = Wo + (size_t)e2 * EE;
    float s = 0.f;
    for (int i = lane; i < EE; i += 32) s += wr[i] * bv[i];
    #pragma unroll
    for (int o = 16; o; o >>= 1) s += __shfl_xor_sync(0xffffffffu, s, o);
    if (lane == 0) g_cvec[e2] = s + bo[e2];
}

// ---------------- MinHash sketches, fused transpose write ----------------
__global__ __launch_bounds__(128) void sketch_kernel(const void* tsq, const void* tsk,
                                                     const void* ha, const void* hb) {
    __shared__ unsigned ids[8][SS];
    int blk = blockIdx.x;
    int row0 = blk * 8;
    int qk = row0 >> 12;
    int r0 = row0 & (BZ * LL - 1);
    int b_ = r0 >> 10, l0 = r0 & (LL - 1);
    int z = qk * BZ + b_;
    int k = threadIdx.x;
    int is64 = g_is64;
    const void* tsel = qk ? tsk : tsq;
    if (k < 64) {
        int rr = k >> 3, s = k & 7;
        ids[rr][s] = is64 ? ((const unsigned*)tsel)[((r0 + rr) * SS + s) * 2]
                          : ((const unsigned*)tsel)[(r0 + rr) * SS + s];
    }
    __syncthreads();
    unsigned res[8];
    if (is64) {
        unsigned a = ((const unsigned*)ha)[2 * k];
        unsigned b = ((const unsigned*)hb)[2 * k];
        #pragma unroll
        for (int rr = 0; rr < 8; rr++) {
            unsigned mn = 0xffffffffu;
            #pragma unroll
            for (int s = 0; s < SS; s++) {
                unsigned long long x = (unsigned long long)ids[rr][s] * a + b;
                unsigned t = (unsigned)(x >> 31) + ((unsigned)x & 0x7fffffffu);
                t = min(t, t - PRIME);
                mn = min(mn, t);
            }
            res[rr] = mn;
        }
    } else {
        unsigned a = ((const unsigned*)ha)[k];
        unsigned b = ((const unsigned*)hb)[k];
        #pragma unroll
        for (int rr = 0; rr < 8; rr++) {
            unsigned mn = 0xffffffffu;
            #pragma unroll
            for (int s = 0; s < SS; s++) {
                unsigned xu = ids[rr][s] * a + b;
                int x = (int)xu;
                long long m = (long long)x % (long long)PRIME;
                if (m < 0) m += (long long)PRIME;
                mn = min(mn, (unsigned)m);
            }
            res[rr] = mn;
        }
    }
    unsigned* dst = g_sigT + ((size_t)z * KH + k) * LL + l0;
    *(uint4*)dst       = make_uint4(res[0], res[1], res[2], res[3]);
    *(uint4*)(dst + 4) = make_uint4(res[4], res[5], res[6], res[7]);
}

// ---------------- hash join: bounded probing, divergence-free probe ----------
__global__ __launch_bounds__(512) void hashjoin_kernel() {
    __shared__ unsigned tval[TBL];
    __shared__ unsigned short trow2[TBL];
    __shared__ unsigned ovf_v[MAXOVF];
    __shared__ unsigned short ovf_r[MAXOVF];
    __shared__ int n_ovf;
    int k = blockIdx.x, b = blockIdx.y;
    int tid = threadIdx.x;
    if (tid == 0) n_ovf = 0;
    #pragma unroll
    for (int i = tid; i < TBL; i += 512) tval[i] = EMPTYV;
    __syncthreads();
    const unsigned* SK = g_sigT + ((size_t)((BZ + b) * KH + k)) * LL;
    const unsigned* SQ = g_sigT + ((size_t)(b * KH + k)) * LL;

    for (int j = tid; j < LL; j += 512) {
        unsigned v = SK[j];
        unsigned x = v; x ^= x >> 16; x *= 0x85ebca6bu; x ^= x >> 13;
        int h = (int)(x & (TMASK & ~3));
        bool done = false;
        #pragma unroll
        for (int p = 0; p < 8; p++) {
            if (!done) {
                int s = (h + p) & TMASK;
                unsigned old = atomicCAS(&tval[s], EMPTYV, v);
                if (old == EMPTYV) { trow2[s] = (unsigned short)j; done = true; }
            }
        }
        if (!done) {
            int pos = atomicAdd(&n_ovf, 1);
            ovf_v[pos] = v; ovf_r[pos] = (unsigned short)j;
        }
    }
    __syncthreads();
    int nov = n_ovf;

    for (int i = tid; i < LL; i += 512) {
        unsigned v = SQ[i];
        unsigned x = v; x ^= x >> 16; x *= 0x85ebca6bu; x ^= x >> 13;
        int h = (int)(x & (TMASK & ~3));
        uint4 t0 = *(const uint4*)&tval[h];
        uint4 t1 = *(const uint4*)&tval[(h + 4) & TMASK];
        unsigned tv[8] = {t0.x, t0.y, t0.z, t0.w, t1.x, t1.y, t1.z, t1.w};
        #pragma unroll
        for (int p = 0; p < 8; p++) {
            if (tv[p] == v) {
                int s = (h + p) & TMASK;
                int row = b * LL + i;
                int pos = atomicAdd(&g_evc[row], 1);
                if (pos < EVCAP) g_evj[(size_t)row * EVCAP + pos] = trow2[s];
            }
        }
        for (int o = 0; o < nov; o++) {
            if (ovf_v[o] == v) {
                int row = b * LL + i;
                int pos = atomicAdd(&g_evc[row], 1);
                if (pos < EVCAP) g_evj[(size_t)row * EVCAP + pos] = ovf_r[o];
            }
        }
    }
}

// ---------------- M2 GEMM (NN), splitK=4 ----------------
__global__ __launch_bounds__(256) void gemm_M2_kernel(const float* __restrict__ Wo,
                                                      const float* __restrict__ Wv) {
    __shared__ float As[16][68];
    __shared__ float Bs[16][68];
    int tid = threadIdx.x;
    int mi = tid & 15, ni = tid >> 4;
    int i0 = blockIdx.x * 64, j0 = blockIdx.y * 64;
    int kz = blockIdx.z;
    float acc[4][4] = {};
    for (int k0 = kz * 128; k0 < kz * 128 + 128; k0 += 16) {
        {
            int ar = tid >> 2, ac = tid & 3;
            float4 v = *(const float4*)&Wo[(size_t)(i0 + ar) * EE + k0 + ac * 4];
            As[ac * 4 + 0][ar] = v.x; As[ac * 4 + 1][ar] = v.y;
            As[ac * 4 + 2][ar] = v.z; As[ac * 4 + 3][ar] = v.w;
        }
        {
            int kk = tid >> 4, jseg = tid & 15;
            *(float4*)&Bs[kk][jseg * 4] =
                *(const float4*)&Wv[(size_t)(k0 + kk) * EE + j0 + jseg * 4];
        }
        __syncthreads();
        #pragma unroll
        for (int k = 0; k < 16; k++) {
            float4 a4 = *(float4*)&As[k][mi * 4];
            float4 b4 = *(float4*)&Bs[k][ni * 4];
            float a[4] = {a4.x, a4.y, a4.z, a4.w};
            float bb[4] = {b4.x, b4.y, b4.z, b4.w};
            #pragma unroll
            for (int r = 0; r < 4; r++)
                #pragma unroll
                for (int c = 0; c < 4; c++)
                    acc[r][c] += a[r] * bb[c];
        }
        __syncthreads();
    }
    float* outp = g_Mpart + (size_t)kz * EE * EE;
    #pragma unroll
    for (int r = 0; r < 4; r++) {
        float4 o = make_float4(acc[r][0], acc[r][1], acc[r][2], acc[r][3]);
        *(float4*)&outp[(size_t)(i0 + mi * 4 + r) * EE + j0 + ni * 4] = o;
    }
}

__global__ void reduceM_kernel() {
    int idx = blockIdx.x * 256 + threadIdx.x;
    g_M[idx] = g_Mpart[idx] + g_Mpart[idx + EE * EE]
             + g_Mpart[idx + 2 * EE * EE] + g_Mpart[idx + 3 * EE * EE];
}

// ---------------- u GEMM (f32x2, R5 measured-best config) ---------------------
__global__ __launch_bounds__(256) void gemm_u_kernel(const float* __restrict__ value) {
    __shared__ float As[16][132];
    __shared__ float Bs[16][132];
    int tid = threadIdx.x;
    int mi = tid & 15, ni = tid >> 4;
    int rt = blockIdx.x;
    int b = rt >> 3;
    int i0 = (rt & 7) * 128;
    int j0 = blockIdx.y * 128;
    const float* A = value + ((size_t)(b * LL) + i0) * EE;
    const float* B = g_M + (size_t)j0 * EE;

    unsigned long long acc[2][2][2][4];
    #pragma unroll
    for (int rh = 0; rh < 2; rh++)
        #pragma unroll
        for (int rp = 0; rp < 2; rp++)
            #pragma unroll
            for (int ch = 0; ch < 2; ch++)
                #pragma unroll
                for (int cc = 0; cc < 4; cc++)
                    acc[rh][rp][ch][cc] = 0ULL;

    int sr = tid >> 2, sc = tid & 3;
    float4 pa0, pa1, pb0, pb1;
    pa0 = *(const float4*)(A + (size_t)sr * EE + sc * 4);
    pa1 = *(const float4*)(A + (size_t)(sr + 64) * EE + sc * 4);
    pb0 = *(const float4*)(B + (size_t)sr * EE + sc * 4);
    pb1 = *(const float4*)(B + (size_t)(sr + 64) * EE + sc * 4);

    for (int t = 0; t < 32; t++) {
        As[sc * 4 + 0][sr] = pa0.x; As[sc * 4 + 1][sr] = pa0.y;
        As[sc * 4 + 2][sr] = pa0.z; As[sc * 4 + 3][sr] = pa0.w;
        As[sc * 4 + 0][sr + 64] = pa1.x; As[sc * 4 + 1][sr + 64] = pa1.y;
        As[sc * 4 + 2][sr + 64] = pa1.z; As[sc * 4 + 3][sr + 64] = pa1.w;
        Bs[sc * 4 + 0][sr] = pb0.x; Bs[sc * 4 + 1][sr] = pb0.y;
        Bs[sc * 4 + 2][sr] = pb0.z; Bs[sc * 4 + 3][sr] = pb0.w;
        Bs[sc * 4 + 0][sr + 64] = pb1.x; Bs[sc * 4 + 1][sr + 64] = pb1.y;
        Bs[sc * 4 + 2][sr + 64] = pb1.z; Bs[sc * 4 + 3][sr + 64] = pb1.w;
        __syncthreads();
        if (t < 31) {
            int k0 = (t + 1) * 16;
            pa0 = *(const float4*)(A + (size_t)sr * EE + k0 + sc * 4);
            pa1 = *(const float4*)(A + (size_t)(sr + 64) * EE + k0 + sc * 4);
            pb0 = *(const float4*)(B + (size_t)sr * EE + k0 + sc * 4);
            pb1 = *(const float4*)(B + (size_t)(sr + 64) * EE + k0 + sc * 4);
        }
        #pragma unroll
        for (int kk = 0; kk < 16; kk++) {
            float4 a0 = *(float4*)&As[kk][mi * 4];
            float4 a1 = *(float4*)&As[kk][64 + mi * 4];
            float4 b0 = *(float4*)&Bs[kk][ni * 4];
            float4 b1 = *(float4*)&Bs[kk][64 + ni * 4];
            unsigned long long pa[2][2], pb[2][4];
            pa[0][0] = pk_ab(a0.x, a0.y); pa[0][1] = pk_ab(a0.z, a0.w);
            pa[1][0] = pk_ab(a1.x, a1.y); pa[1][1] = pk_ab(a1.z, a1.w);
            pb[0][0] = pk_dup(b0.x); pb[0][1] = pk_dup(b0.y);
            pb[0][2] = pk_dup(b0.z); pb[0][3] = pk_dup(b0.w);
            pb[1][0] = pk_dup(b1.x); pb[1][1] = pk_dup(b1.y);
            pb[1][2] = pk_dup(b1.z); pb[1][3] = pk_dup(b1.w);
            #pragma unroll
            for (int rh = 0; rh < 2; rh++)
                #pragma unroll
                for (int rp = 0; rp < 2; rp++)
                    #pragma unroll
                    for (int ch = 0; ch < 2; ch++)
                        #pragma unroll
                        for (int cc = 0; cc < 4; cc++)
                            ffma2(acc[rh][rp][ch][cc], pa[rh][rp], pb[ch][cc]);
        }
        __syncthreads();
    }

    #pragma unroll
    for (int rh = 0; rh < 2; rh++)
        #pragma unroll
        for (int rp = 0; rp < 2; rp++)
            #pragma unroll
            for (int h = 0; h < 2; h++) {
                int row = i0 + rh * 64 + mi * 4 + 2 * rp + h;
                float* orow = g_u + ((size_t)(b * LL) + row) * EE + j0;
                #pragma unroll
                for (int ch = 0; ch < 2; ch++) {
                    float2 v0 = up2(acc[rh][rp][ch][0]);
                    float2 v1 = up2(acc[rh][rp][ch][1]);
                    float2 v2 = up2(acc[rh][rp][ch][2]);
                    float2 v3 = up2(acc[rh][rp][ch][3]);
                    float4 o = h ? make_float4(v0.y, v1.y, v2.y, v3.y)
                                 : make_float4(v0.x, v1.x, v2.x, v3.x);
                    *(float4*)(orow + ch * 64 + ni * 4) = o;
                }
            }
}

// ---------------- dense-term chain ----------------
__global__ __launch_bounds__(256) void vsum1_kernel(const float* __restrict__ value) {
    int b = blockIdx.y, lc = blockIdx.x;
    const float* vp = value + ((size_t)b * LL + lc * 64) * EE;
    int e = threadIdx.x;
    float a0 = 0.f, a1 = 0.f;
    for (int r = 0; r < 64; r++) {
        a0 += vp[(size_t)r * EE + e];
        a1 += vp[(size_t)r * EE + e + 256];
    }
    g_vsumP[(size_t)(b * 16 + lc) * EE + e] = a0;
    g_vsumP[(size_t)(b * 16 + lc) * EE + e + 256] = a1;
}
__global__ void vsum2_kernel() {
    int b = blockIdx.y;
    int e = blockIdx.x * 128 + threadIdx.x;
    float s = 0.f;
    for (int c = 0; c < 16; c++) s += g_vsumP[(size_t)(b * 16 + c) * EE + e];
    g_vsum[b * EE + e] = s;
}
__global__ __launch_bounds__(256) void usum_kernel() {
    int b = blockIdx.y;
    int e2 = blockIdx.x * 8 + (threadIdx.x >> 5);
    int lane = threadIdx.x & 31;
    const float* mr = g_M + (size_t)e2 * EE;
    const float* vs = g_vsum + b * EE;
    float s = 0.f;
    for (int i = lane; i < EE; i += 32) s += mr[i] * vs[i];
    #pragma unroll
    for (int o = 16; o; o >>= 1) s += __shfl_xor_sync(0xffffffffu, s, o);
    if (lane == 0) g_usum[b * EE + e2] = s;
}

// ---------------- per-row: sort events, aggregate runs, denom ----------------
__global__ __launch_bounds__(256) void build_sparse_kernel() {
    __shared__ int buf[8][EVCAP];
    int w = threadIdx.x >> 5;
    int lane = threadIdx.x & 31;
    int row = blockIdx.x * 8 + w;
    int n = g_evc[row];
    if (n > EVCAP) n = EVCAP;
    int* bw = buf[w];
    for (int p = lane; p < EVCAP; p += 32)
        bw[p] = (p < n) ? g_evj[(size_t)row * EVCAP + p] : 0x7fffffff;
    __syncwarp();
    for (int pass = 0; pass < n; pass++) {
        int start = pass & 1;
        for (int p = start + lane * 2; p + 1 < n; p += 64) {
            int a = bw[p], c = bw[p + 1];
            if (c < a) { bw[p] = c; bw[p + 1] = a; }
        }
        __syncwarp();
    }
    if (lane == 0) {
        float lut0 = g_lut[0];
        float corr = 0.f;
        int base = 0;
        int* oi = g_nzi + (size_t)row * EVCAP;
        float* ow = g_nzw + (size_t)row * EVCAP;
        int p = 0;
        while (p < n) {
            int j = bw[p];
            int m = 1;
            while (p + m < n && bw[p + m] == j) m++;
            float wgt = g_lut[m] - lut0;
            oi[base] = j;
            ow[base] = wgt;
            corr += wgt;
            base++;
            p += m;
        }
        g_nzc[row] = base;
        g_rowinv[row] = 1.0f / (1024.0f * lut0 + corr);
    }
}

// ---------------- output ----------------
__global__ __launch_bounds__(128) void out_kernel(float* __restrict__ out) {
    int row = blockIdx.x;
    int b = row >> 10;
    int e4 = threadIdx.x;
    float lut0 = g_lut[0];
    float4 us = ((const float4*)g_usum)[b * 128 + e4];
    float4 acc = make_float4(us.x * lut0, us.y * lut0, us.z * lut0, us.w * lut0);
    int n = g_nzc[row];
    const int* oi = g_nzi + (size_t)row * EVCAP;
    const float* ow = g_nzw + (size_t)row * EVCAP;
    const float4* ub = (const float4*)g_u + (size_t)b * LL * 128;
    for (int t = 0; t < n; t++) {
        int j = oi[t];
        float w = ow[t];
        float4 u4 = ub[(size_t)j * 128 + e4];
        acc.x += w * u4.x; acc.y += w * u4.y;
        acc.z += w * u4.z; acc.w += w * u4.w;
    }
    float inv = g_rowinv[row];
    float4 cc = ((const float4*)g_cvec)[e4];
    float4 o = make_float4(acc.x * inv + cc.x, acc.y * inv + cc.y,
                           acc.z * inv + cc.z, acc.w * inv + cc.w);
    ((float4*)out)[(size_t)row * 128 + e4] = o;
}

// ---------------- launch: forked-graph schedule ----------------
extern "C" void kernel_launch(void* const* d_in, const int* in_sizes, int n_in,
                              void* d_out, int out_size) {
    const float* value = (const float*)d_in[2];
    const void*  tsq   = d_in[3];
    const void*  tsk   = d_in[4];
    const void*  ha    = d_in[5];
    const void*  hb    = d_in[6];
    const float* Wv    = (const float*)d_in[11];
    const float* bv    = (const float*)d_in[12];
    const float* Wo    = (const float*)d_in[13];
    const float* bo    = (const float*)d_in[14];
    float* out = (float*)d_out;

    // trunk
    init_kernel<<<81, 256>>>(ha, Wo, bv, bo);                               // 0
    cudaEventRecord(HX.e0, 0);
    cudaStreamWaitEvent(HX.s1, HX.e0, 0);
    cudaStreamWaitEvent(HX.s2, HX.e0, 0);

    // chain A (stream s1): M2 -> reduceM -> gemm_u
    gemm_M2_kernel<<<dim3(8, 8, 4), 256, 0, HX.s1>>>(Wo, Wv);               // 1
    reduceM_kernel<<<EE * EE / 256, 256, 0, HX.s1>>>();                     // 2
    gemm_u_kernel<<<dim3(BZ * LL / 128, EE / 128), 256, 0, HX.s1>>>(value); // 3

    // chain B (stream s2): sketch -> hashjoin -> build_sparse -> vsum1 -> vsum2
    sketch_kernel<<<2 * BZ * LL / 8, 128, 0, HX.s2>>>(tsq, tsk, ha, hb);    // 4
    hashjoin_kernel<<<dim3(KH, BZ), 512, 0, HX.s2>>>();                     // 5
    build_sparse_kernel<<<BZ * LL / 8, 256, 0, HX.s2>>>();                  // 6
    vsum1_kernel<<<dim3(16, BZ), 256, 0, HX.s2>>>(value);                   // 7
    vsum2_kernel<<<dim3(EE / 128, BZ), 128, 0, HX.s2>>>();                  // 8

    // join
    cudaEventRecord(HX.e1, HX.s1);
    cudaEventRecord(HX.e2, HX.s2);
    cudaStreamWaitEvent(0, HX.e1, 0);
    cudaStreamWaitEvent(0, HX.e2, 0);

    usum_kernel<<<dim3(EE / 8, BZ), 256>>>();                               // 9
    out_kernel<<<BZ * LL, 128>>>(out);                                      // 10
}

// round 14
// speedup vs baseline: 1.1525x; 1.1525x over previous
#include <cuda_runtime.h>
#include <cuda_bf16.h>
#include <stdint.h>

#define BZ 4
#define LL 1024
#define SS 8
#define KH 128
#define EE 512
#define PRIME 2147483647u
#define EMPTYV 0xffffffffu
#define EVCAP 256
#define TBL 4096
#define TMASK 4095
#define MAXOVF 1024

// ---------------- device scratch ----------------
__device__ __align__(16) unsigned int  g_sigT[2 * BZ * KH * LL];   // [z][k][l]
__device__ float         g_lut[129];
__device__ int           g_is64;
__device__ __align__(16) float         g_Mpart[4 * EE * EE];
__device__ __align__(16) float         g_M[EE * EE];        // M2 [e2][e1] fp32
__device__ __align__(16) float         g_u[BZ * LL * EE];   // u fp32 [b][r][e2]
__device__ __align__(16) float         g_vsumP[16 * BZ * EE];
__device__ __align__(16) float         g_usum[BZ * EE];
__device__ __align__(16) float         g_cvec[EE];
__device__ float         g_rowinv[BZ * LL];
__device__ int           g_evc[BZ * LL];
__device__ __align__(16) int           g_evj[BZ * LL * EVCAP];
__device__ int           g_nzc[BZ * LL];
__device__ __align__(16) int           g_nzi[BZ * LL * EVCAP];
__device__ __align__(16) float         g_nzw[BZ * LL * EVCAP];

// ---------------- f32x2 helpers ----------------
__device__ __forceinline__ unsigned long long pk_dup(float x) {
    unsigned long long d;
    unsigned u = __float_as_uint(x);
    asm("mov.b64 %0, {%1, %1};" : "=l"(d) : "r"(u));
    return d;
}
__device__ __forceinline__ unsigned long long pk_ab(float x, float y) {
    unsigned long long d;
    asm("mov.b64 %0, {%1, %2};" : "=l"(d) : "r"(__float_as_uint(x)), "r"(__float_as_uint(y)));
    return d;
}
__device__ __forceinline__ void ffma2(unsigned long long& d, unsigned long long a,
                                      unsigned long long b) {
    asm("fma.rn.f32x2 %0, %1, %2, %0;" : "+l"(d) : "l"(a), "l"(b));
}
__device__ __forceinline__ float2 up2(unsigned long long d) {
    unsigned lo, hi;
    asm("mov.b64 {%0, %1}, %2;" : "=r"(lo), "=r"(hi) : "l"(d));
    return make_float2(__uint_as_float(lo), __uint_as_float(hi));
}

// ---------------- init: dtype detect + LUT + zero evc + cvec ----------------
__global__ __launch_bounds__(256) void init_kernel(const void* ha,
                                                   const float* __restrict__ Wo,
                                                   const float* __restrict__ bv,
                                                   const float* __restrict__ bo) {
    int bid = blockIdx.x;
    if (bid == 0) {
        int t = threadIdx.x;
        if (t == 0) {
            const int* p = (const int*)ha;
            int is64 = 1;
            for (int i = 0; i < 16; i++)
                if (p[2 * i + 1] != 0) is64 = 0;
            g_is64 = is64;
        }
        if (t < 129) {
            float j = (float)t / 128.0f;
            float delta = 16.0f * (1.0f - j) / (1.0f + j);
            float s = expf(-0.3f * delta);
            g_lut[t] = expf(s);
        }
        return;
    }
    if (bid <= 16) {
        g_evc[(bid - 1) * 256 + threadIdx.x] = 0;
        return;
    }
    int e2 = (bid - 17) * 8 + (threadIdx.x >> 5);
    int lane = threadIdx.x & 31;
    const float* wr = Wo + (size_t)e2 * EE;
    float s = 0.f;
    for (int i = lane; i < EE; i += 32) s += wr[i] * bv[i];
    #pragma unroll
    for (int o = 16; o; o >>= 1) s += __shfl_xor_sync(0xffffffffu, s, o);
    if (lane == 0) g_cvec[e2] = s + bo[e2];
}

// ---------------- MinHash sketches, fused transpose write ----------------
__global__ __launch_bounds__(128) void sketch_kernel(const void* tsq, const void* tsk,
                                                     const void* ha, const void* hb) {
    __shared__ unsigned ids[8][SS];
    int blk = blockIdx.x;
    int row0 = blk * 8;
    int qk = row0 >> 12;
    int r0 = row0 & (BZ * LL - 1);
    int b_ = r0 >> 10, l0 = r0 & (LL - 1);
    int z = qk * BZ + b_;
    int k = threadIdx.x;
    int is64 = g_is64;
    const void* tsel = qk ? tsk : tsq;
    if (k < 64) {
        int rr = k >> 3, s = k & 7;
        ids[rr][s] = is64 ? ((const unsigned*)tsel)[((r0 + rr) * SS + s) * 2]
                          : ((const unsigned*)tsel)[(r0 + rr) * SS + s];
    }
    __syncthreads();
    unsigned res[8];
    if (is64) {
        unsigned a = ((const unsigned*)ha)[2 * k];
        unsigned b = ((const unsigned*)hb)[2 * k];
        #pragma unroll
        for (int rr = 0; rr < 8; rr++) {
            unsigned mn = 0xffffffffu;
            #pragma unroll
            for (int s = 0; s < SS; s++) {
                unsigned long long x = (unsigned long long)ids[rr][s] * a + b;
                unsigned t = (unsigned)(x >> 31) + ((unsigned)x & 0x7fffffffu);
                t = min(t, t - PRIME);
                mn = min(mn, t);
            }
            res[rr] = mn;
        }
    } else {
        unsigned a = ((const unsigned*)ha)[k];
        unsigned b = ((const unsigned*)hb)[k];
        #pragma unroll
        for (int rr = 0; rr < 8; rr++) {
            unsigned mn = 0xffffffffu;
            #pragma unroll
            for (int s = 0; s < SS; s++) {
                unsigned xu = ids[rr][s] * a + b;
                int x = (int)xu;
                long long m = (long long)x % (long long)PRIME;
                if (m < 0) m += (long long)PRIME;
                mn = min(mn, (unsigned)m);
            }
            res[rr] = mn;
        }
    }
    unsigned* dst = g_sigT + ((size_t)z * KH + k) * LL + l0;
    *(uint4*)dst       = make_uint4(res[0], res[1], res[2], res[3]);
    *(uint4*)(dst + 4) = make_uint4(res[4], res[5], res[6], res[7]);
}

// ---------------- hash join: bounded probing, divergence-free probe ----------
__global__ __launch_bounds__(512) void hashjoin_kernel() {
    __shared__ unsigned tval[TBL];
    __shared__ unsigned short trow2[TBL];
    __shared__ unsigned ovf_v[MAXOVF];
    __shared__ unsigned short ovf_r[MAXOVF];
    __shared__ int n_ovf;
    int k = blockIdx.x, b = blockIdx.y;
    int tid = threadIdx.x;
    if (tid == 0) n_ovf = 0;
    #pragma unroll
    for (int i = tid; i < TBL; i += 512) tval[i] = EMPTYV;
    __syncthreads();
    const unsigned* SK = g_sigT + ((size_t)((BZ + b) * KH + k)) * LL;
    const unsigned* SQ = g_sigT + ((size_t)(b * KH + k)) * LL;

    for (int j = tid; j < LL; j += 512) {
        unsigned v = SK[j];
        unsigned x = v; x ^= x >> 16; x *= 0x85ebca6bu; x ^= x >> 13;
        int h = (int)(x & (TMASK & ~3));
        bool done = false;
        #pragma unroll
        for (int p = 0; p < 8; p++) {
            if (!done) {
                int s = (h + p) & TMASK;
                unsigned old = atomicCAS(&tval[s], EMPTYV, v);
                if (old == EMPTYV) { trow2[s] = (unsigned short)j; done = true; }
            }
        }
        if (!done) {
            int pos = atomicAdd(&n_ovf, 1);
            ovf_v[pos] = v; ovf_r[pos] = (unsigned short)j;
        }
    }
    __syncthreads();
    int nov = n_ovf;

    for (int i = tid; i < LL; i += 512) {
        unsigned v = SQ[i];
        unsigned x = v; x ^= x >> 16; x *= 0x85ebca6bu; x ^= x >> 13;
        int h = (int)(x & (TMASK & ~3));
        uint4 t0 = *(const uint4*)&tval[h];
        uint4 t1 = *(const uint4*)&tval[(h + 4) & TMASK];
        unsigned tv[8] = {t0.x, t0.y, t0.z, t0.w, t1.x, t1.y, t1.z, t1.w};
        #pragma unroll
        for (int p = 0; p < 8; p++) {
            if (tv[p] == v) {
                int s = (h + p) & TMASK;
                int row = b * LL + i;
                int pos = atomicAdd(&g_evc[row], 1);
                if (pos < EVCAP) g_evj[(size_t)row * EVCAP + pos] = trow2[s];
            }
        }
        for (int o = 0; o < nov; o++) {
            if (ovf_v[o] == v) {
                int row = b * LL + i;
                int pos = atomicAdd(&g_evc[row], 1);
                if (pos < EVCAP) g_evj[(size_t)row * EVCAP + pos] = ovf_r[o];
            }
        }
    }
}

// ---------------- per-row: sort events, aggregate runs, denom ----------------
__global__ __launch_bounds__(256) void build_sparse_kernel() {
    __shared__ int buf[8][EVCAP];
    int w = threadIdx.x >> 5;
    int lane = threadIdx.x & 31;
    int row = blockIdx.x * 8 + w;
    int n = g_evc[row];
    if (n > EVCAP) n = EVCAP;
    int* bw = buf[w];
    for (int p = lane; p < EVCAP; p += 32)
        bw[p] = (p < n) ? g_evj[(size_t)row * EVCAP + p] : 0x7fffffff;
    __syncwarp();
    for (int pass = 0; pass < n; pass++) {
        int start = pass & 1;
        for (int p = start + lane * 2; p + 1 < n; p += 64) {
            int a = bw[p], c = bw[p + 1];
            if (c < a) { bw[p] = c; bw[p + 1] = a; }
        }
        __syncwarp();
    }
    if (lane == 0) {
        float lut0 = g_lut[0];
        float corr = 0.f;
        int base = 0;
        int* oi = g_nzi + (size_t)row * EVCAP;
        float* ow = g_nzw + (size_t)row * EVCAP;
        int p = 0;
        while (p < n) {
            int j = bw[p];
            int m = 1;
            while (p + m < n && bw[p + m] == j) m++;
            float wgt = g_lut[m] - lut0;
            oi[base] = j;
            ow[base] = wgt;
            corr += wgt;
            base++;
            p += m;
        }
        g_nzc[row] = base;
        g_rowinv[row] = 1.0f / (1024.0f * lut0 + corr);
    }
}

// ---------------- M2 GEMM (NN), splitK=4 ----------------
__global__ __launch_bounds__(256) void gemm_M2_kernel(const float* __restrict__ Wo,
                                                      const float* __restrict__ Wv) {
    __shared__ float As[16][68];
    __shared__ float Bs[16][68];
    int tid = threadIdx.x;
    int mi = tid & 15, ni = tid >> 4;
    int i0 = blockIdx.x * 64, j0 = blockIdx.y * 64;
    int kz = blockIdx.z;
    float acc[4][4] = {};
    for (int k0 = kz * 128; k0 < kz * 128 + 128; k0 += 16) {
        {
            int ar = tid >> 2, ac = tid & 3;
            float4 v = *(const float4*)&Wo[(size_t)(i0 + ar) * EE + k0 + ac * 4];
            As[ac * 4 + 0][ar] = v.x; As[ac * 4 + 1][ar] = v.y;
            As[ac * 4 + 2][ar] = v.z; As[ac * 4 + 3][ar] = v.w;
        }
        {
            int kk = tid >> 4, jseg = tid & 15;
            *(float4*)&Bs[kk][jseg * 4] =
                *(const float4*)&Wv[(size_t)(k0 + kk) * EE + j0 + jseg * 4];
        }
        __syncthreads();
        #pragma unroll
        for (int k = 0; k < 16; k++) {
            float4 a4 = *(float4*)&As[k][mi * 4];
            float4 b4 = *(float4*)&Bs[k][ni * 4];
            float a[4] = {a4.x, a4.y, a4.z, a4.w};
            float bb[4] = {b4.x, b4.y, b4.z, b4.w};
            #pragma unroll
            for (int r = 0; r < 4; r++)
                #pragma unroll
                for (int c = 0; c < 4; c++)
                    acc[r][c] += a[r] * bb[c];
        }
        __syncthreads();
    }
    float* outp = g_Mpart + (size_t)kz * EE * EE;
    #pragma unroll
    for (int r = 0; r < 4; r++) {
        float4 o = make_float4(acc[r][0], acc[r][1], acc[r][2], acc[r][3]);
        *(float4*)&outp[(size_t)(i0 + mi * 4 + r) * EE + j0 + ni * 4] = o;
    }
}

__global__ void reduceM_kernel() {
    int idx = blockIdx.x * 256 + threadIdx.x;
    g_M[idx] = g_Mpart[idx] + g_Mpart[idx + EE * EE]
             + g_Mpart[idx + 2 * EE * EE] + g_Mpart[idx + 3 * EE * EE];
}

// ---------------- u GEMM (f32x2, R5 measured-best config) ---------------------
__global__ __launch_bounds__(256) void gemm_u_kernel(const float* __restrict__ value) {
    __shared__ float As[16][132];
    __shared__ float Bs[16][132];
    int tid = threadIdx.x;
    int mi = tid & 15, ni = tid >> 4;
    int rt = blockIdx.x;
    int b = rt >> 3;
    int i0 = (rt & 7) * 128;
    int j0 = blockIdx.y * 128;
    const float* A = value + ((size_t)(b * LL) + i0) * EE;
    const float* B = g_M + (size_t)j0 * EE;

    unsigned long long acc[2][2][2][4];
    #pragma unroll
    for (int rh = 0; rh < 2; rh++)
        #pragma unroll
        for (int rp = 0; rp < 2; rp++)
            #pragma unroll
            for (int ch = 0; ch < 2; ch++)
                #pragma unroll
                for (int cc = 0; cc < 4; cc++)
                    acc[rh][rp][ch][cc] = 0ULL;

    int sr = tid >> 2, sc = tid & 3;
    float4 pa0, pa1, pb0, pb1;
    pa0 = *(const float4*)(A + (size_t)sr * EE + sc * 4);
    pa1 = *(const float4*)(A + (size_t)(sr + 64) * EE + sc * 4);
    pb0 = *(const float4*)(B + (size_t)sr * EE + sc * 4);
    pb1 = *(const float4*)(B + (size_t)(sr + 64) * EE + sc * 4);

    for (int t = 0; t < 32; t++) {
        As[sc * 4 + 0][sr] = pa0.x; As[sc * 4 + 1][sr] = pa0.y;
        As[sc * 4 + 2][sr] = pa0.z; As[sc * 4 + 3][sr] = pa0.w;
        As[sc * 4 + 0][sr + 64] = pa1.x; As[sc * 4 + 1][sr + 64] = pa1.y;
        As[sc * 4 + 2][sr + 64] = pa1.z; As[sc * 4 + 3][sr + 64] = pa1.w;
        Bs[sc * 4 + 0][sr] = pb0.x; Bs[sc * 4 + 1][sr] = pb0.y;
        Bs[sc * 4 + 2][sr] = pb0.z; Bs[sc * 4 + 3][sr] = pb0.w;
        Bs[sc * 4 + 0][sr + 64] = pb1.x; Bs[sc * 4 + 1][sr + 64] = pb1.y;
        Bs[sc * 4 + 2][sr + 64] = pb1.z; Bs[sc * 4 + 3][sr + 64] = pb1.w;
        __syncthreads();
        if (t < 31) {
            int k0 = (t + 1) * 16;
            pa0 = *(const float4*)(A + (size_t)sr * EE + k0 + sc * 4);
            pa1 = *(const float4*)(A + (size_t)(sr + 64) * EE + k0 + sc * 4);
            pb0 = *(const float4*)(B + (size_t)sr * EE + k0 + sc * 4);
            pb1 = *(const float4*)(B + (size_t)(sr + 64) * EE + k0 + sc * 4);
        }
        #pragma unroll
        for (int kk = 0; kk < 16; kk++) {
            float4 a0 = *(float4*)&As[kk][mi * 4];
            float4 a1 = *(float4*)&As[kk][64 + mi * 4];
            float4 b0 = *(float4*)&Bs[kk][ni * 4];
            float4 b1 = *(float4*)&Bs[kk][64 + ni * 4];
            unsigned long long pa[2][2], pb[2][4];
            pa[0][0] = pk_ab(a0.x, a0.y); pa[0][1] = pk_ab(a0.z, a0.w);
            pa[1][0] = pk_ab(a1.x, a1.y); pa[1][1] = pk_ab(a1.z, a1.w);
            pb[0][0] = pk_dup(b0.x); pb[0][1] = pk_dup(b0.y);
            pb[0][2] = pk_dup(b0.z); pb[0][3] = pk_dup(b0.w);
            pb[1][0] = pk_dup(b1.x); pb[1][1] = pk_dup(b1.y);
            pb[1][2] = pk_dup(b1.z); pb[1][3] = pk_dup(b1.w);
            #pragma unroll
            for (int rh = 0; rh < 2; rh++)
                #pragma unroll
                for (int rp = 0; rp < 2; rp++)
                    #pragma unroll
                    for (int ch = 0; ch < 2; ch++)
                        #pragma unroll
                        for (int cc = 0; cc < 4; cc++)
                            ffma2(acc[rh][rp][ch][cc], pa[rh][rp], pb[ch][cc]);
        }
        __syncthreads();
    }

    #pragma unroll
    for (int rh = 0; rh < 2; rh++)
        #pragma unroll
        for (int rp = 0; rp < 2; rp++)
            #pragma unroll
            for (int h = 0; h < 2; h++) {
                int row = i0 + rh * 64 + mi * 4 + 2 * rp + h;
                float* orow = g_u + ((size_t)(b * LL) + row) * EE + j0;
                #pragma unroll
                for (int ch = 0; ch < 2; ch++) {
                    float2 v0 = up2(acc[rh][rp][ch][0]);
                    float2 v1 = up2(acc[rh][rp][ch][1]);
                    float2 v2 = up2(acc[rh][rp][ch][2]);
                    float2 v3 = up2(acc[rh][rp][ch][3]);
                    float4 o = h ? make_float4(v0.y, v1.y, v2.y, v3.y)
                                 : make_float4(v0.x, v1.x, v2.x, v3.x);
                    *(float4*)(orow + ch * 64 + ni * 4) = o;
                }
            }
}

// ---------------- dense-term chain ----------------
__global__ __launch_bounds__(256) void vsum1_kernel(const float* __restrict__ value) {
    int b = blockIdx.y, lc = blockIdx.x;
    const float* vp = value + ((size_t)b * LL + lc * 64) * EE;
    int e = threadIdx.x;
    float a0 = 0.f, a1 = 0.f;
    for (int r = 0; r < 64; r++) {
        a0 += vp[(size_t)r * EE + e];
        a1 += vp[(size_t)r * EE + e + 256];
    }
    g_vsumP[(size_t)(b * 16 + lc) * EE + e] = a0;
    g_vsumP[(size_t)(b * 16 + lc) * EE + e + 256] = a1;
}
// fused vsum2+usum: block handles 8 e2 for one batch; first reduce partials
__global__ __launch_bounds__(256) void usum_kernel() {
    __shared__ float vs[EE];
    int b = blockIdx.y;
    int t = threadIdx.x;
    {
        float s0 = 0.f, s1 = 0.f;
        for (int c = 0; c < 16; c++) {
            s0 += g_vsumP[(size_t)(b * 16 + c) * EE + t];
            s1 += g_vsumP[(size_t)(b * 16 + c) * EE + t + 256];
        }
        vs[t] = s0;
        vs[t + 256] = s1;
    }
    __syncthreads();
    int e2 = blockIdx.x * 8 + (t >> 5);
    int lane = t & 31;
    const float* mr = g_M + (size_t)e2 * EE;
    float s = 0.f;
    #pragma unroll 4
    for (int i = lane; i < EE; i += 32) s += mr[i] * vs[i];
    #pragma unroll
    for (int o = 16; o; o >>= 1) s += __shfl_xor_sync(0xffffffffu, s, o);
    if (lane == 0) g_usum[b * EE + e2] = s;
}

// ---------------- output ----------------
__global__ __launch_bounds__(128) void out_kernel(float* __restrict__ out) {
    int row = blockIdx.x;
    int b = row >> 10;
    int e4 = threadIdx.x;
    float lut0 = g_lut[0];
    float4 us = ((const float4*)g_usum)[b * 128 + e4];
    float4 acc = make_float4(us.x * lut0, us.y * lut0, us.z * lut0, us.w * lut0);
    int n = g_nzc[row];
    const int* oi = g_nzi + (size_t)row * EVCAP;
    const float* ow = g_nzw + (size_t)row * EVCAP;
    const float4* ub = (const float4*)g_u + (size_t)b * LL * 128;
    for (int t = 0; t < n; t++) {
        int j = oi[t];
        float w = ow[t];
        float4 u4 = ub[(size_t)j * 128 + e4];
        acc.x += w * u4.x; acc.y += w * u4.y;
        acc.z += w * u4.z; acc.w += w * u4.w;
    }
    float inv = g_rowinv[row];
    float4 cc = ((const float4*)g_cvec)[e4];
    float4 o = make_float4(acc.x * inv + cc.x, acc.y * inv + cc.y,
                           acc.z * inv + cc.z, acc.w * inv + cc.w);
    ((float4*)out)[(size_t)row * 128 + e4] = o;
}

// ---------------- launch: serial (measured-best scheduling) ----------------
extern "C" void kernel_launch(void* const* d_in, const int* in_sizes, int n_in,
                              void* d_out, int out_size) {
    const float* value = (const float*)d_in[2];
    const void*  tsq   = d_in[3];
    const void*  tsk   = d_in[4];
    const void*  ha    = d_in[5];
    const void*  hb    = d_in[6];
    const float* Wv    = (const float*)d_in[11];
    const float* bv    = (const float*)d_in[12];
    const float* Wo    = (const float*)d_in[13];
    const float* bo    = (const float*)d_in[14];
    float* out = (float*)d_out;

    init_kernel<<<81, 256>>>(ha, Wo, bv, bo);                           // 0
    sketch_kernel<<<2 * BZ * LL / 8, 128>>>(tsq, tsk, ha, hb);          // 1
    hashjoin_kernel<<<dim3(KH, BZ), 512>>>();                           // 2
    build_sparse_kernel<<<BZ * LL / 8, 256>>>();                        // 3 <- profiled
    gemm_M2_kernel<<<dim3(8, 8, 4), 256>>>(Wo, Wv);                     // 4
    reduceM_kernel<<<EE * EE / 256, 256>>>();                           // 5
    gemm_u_kernel<<<dim3(BZ * LL / 128, EE / 128), 256>>>(value);       // 6
    vsum1_kernel<<<dim3(16, BZ), 256>>>(value);                         // 7
    usum_kernel<<<dim3(EE / 8, BZ), 256>>>();                           // 8
    out_kernel<<<BZ * LL, 128>>>(out);                                  // 9
}

// round 16
// speedup vs baseline: 1.2734x; 1.1049x over previous
#include <cuda_runtime.h>
#include <cuda_bf16.h>
#include <stdint.h>

#define BZ 4
#define LL 1024
#define SS 8
#define KH 128
#define EE 512
#define PRIME 2147483647u
#define EMPTYV 0xffffffffu
#define EVCAP 256
#define TBL 4096
#define TMASK 4095
#define MAXOVF 1024

// ---------------- device scratch ----------------
__device__ __align__(16) unsigned int  g_sigT[2 * BZ * KH * LL];   // [z][k][l]
__device__ float         g_lut[129];
__device__ int           g_is64;
__device__ __align__(16) float         g_Mpart[4 * EE * EE];
__device__ __align__(16) float         g_M[EE * EE];        // M2 [e2][e1] fp32
__device__ __align__(16) float         g_u[BZ * LL * EE];   // u fp32 [b][r][e2]
__device__ __align__(16) float         g_vsumP[16 * BZ * EE];
__device__ __align__(16) float         g_usum[BZ * EE];
__device__ __align__(16) float         g_cvec[EE];
__device__ float         g_rowinv[BZ * LL];
__device__ int           g_evc[BZ * LL];
__device__ __align__(16) int           g_evj[BZ * LL * EVCAP];
__device__ int           g_nzc[BZ * LL];
__device__ __align__(16) int           g_nzi[BZ * LL * EVCAP];
__device__ __align__(16) float         g_nzw[BZ * LL * EVCAP];

// ---------------- f32x2 helpers ----------------
__device__ __forceinline__ unsigned long long pk_dup(float x) {
    unsigned long long d;
    unsigned u = __float_as_uint(x);
    asm("mov.b64 %0, {%1, %1};" : "=l"(d) : "r"(u));
    return d;
}
__device__ __forceinline__ unsigned long long pk_ab(float x, float y) {
    unsigned long long d;
    asm("mov.b64 %0, {%1, %2};" : "=l"(d) : "r"(__float_as_uint(x)), "r"(__float_as_uint(y)));
    return d;
}
__device__ __forceinline__ void ffma2(unsigned long long& d, unsigned long long a,
                                      unsigned long long b) {
    asm("fma.rn.f32x2 %0, %1, %2, %0;" : "+l"(d) : "l"(a), "l"(b));
}
__device__ __forceinline__ float2 up2(unsigned long long d) {
    unsigned lo, hi;
    asm("mov.b64 {%0, %1}, %2;" : "=r"(lo), "=r"(hi) : "l"(d));
    return make_float2(__uint_as_float(lo), __uint_as_float(hi));
}

// ---------------- init: dtype detect + LUT + zero evc + cvec ----------------
__global__ __launch_bounds__(256) void init_kernel(const void* ha,
                                                   const float* __restrict__ Wo,
                                                   const float* __restrict__ bv,
                                                   const float* __restrict__ bo) {
    int bid = blockIdx.x;
    if (bid == 0) {
        int t = threadIdx.x;
        if (t == 0) {
            const int* p = (const int*)ha;
            int is64 = 1;
            for (int i = 0; i < 16; i++)
                if (p[2 * i + 1] != 0) is64 = 0;
            g_is64 = is64;
        }
        if (t < 129) {
            float j = (float)t / 128.0f;
            float delta = 16.0f * (1.0f - j) / (1.0f + j);
            float s = expf(-0.3f * delta);
            g_lut[t] = expf(s);
        }
        return;
    }
    if (bid <= 16) {
        g_evc[(bid - 1) * 256 + threadIdx.x] = 0;
        return;
    }
    int e2 = (bid - 17) * 8 + (threadIdx.x >> 5);
    int lane = threadIdx.x & 31;
    const float* wr = Wo + (size_t)e2 * EE;
    float s = 0.f;
    for (int i = lane; i < EE; i += 32) s += wr[i] * bv[i];
    #pragma unroll
    for (int o = 16; o; o >>= 1) s += __shfl_xor_sync(0xffffffffu, s, o);
    if (lane == 0) g_cvec[e2] = s + bo[e2];
}

// ---------------- MinHash sketches, fused transpose write ----------------
__global__ __launch_bounds__(128) void sketch_kernel(const void* tsq, const void* tsk,
                                                     const void* ha, const void* hb) {
    __shared__ unsigned ids[8][SS];
    int blk = blockIdx.x;
    int row0 = blk * 8;
    int qk = row0 >> 12;
    int r0 = row0 & (BZ * LL - 1);
    int b_ = r0 >> 10, l0 = r0 & (LL - 1);
    int z = qk * BZ + b_;
    int k = threadIdx.x;
    int is64 = g_is64;
    const void* tsel = qk ? tsk : tsq;
    if (k < 64) {
        int rr = k >> 3, s = k & 7;
        ids[rr][s] = is64 ? ((const unsigned*)tsel)[((r0 + rr) * SS + s) * 2]
                          : ((const unsigned*)tsel)[(r0 + rr) * SS + s];
    }
    __syncthreads();
    unsigned res[8];
    if (is64) {
        unsigned a = ((const unsigned*)ha)[2 * k];
        unsigned b = ((const unsigned*)hb)[2 * k];
        #pragma unroll
        for (int rr = 0; rr < 8; rr++) {
            unsigned mn = 0xffffffffu;
            #pragma unroll
            for (int s = 0; s < SS; s++) {
                unsigned long long x = (unsigned long long)ids[rr][s] * a + b;
                unsigned t = (unsigned)(x >> 31) + ((unsigned)x & 0x7fffffffu);
                t = min(t, t - PRIME);
                mn = min(mn, t);
            }
            res[rr] = mn;
        }
    } else {
        unsigned a = ((const unsigned*)ha)[k];
        unsigned b = ((const unsigned*)hb)[k];
        #pragma unroll
        for (int rr = 0; rr < 8; rr++) {
            unsigned mn = 0xffffffffu;
            #pragma unroll
            for (int s = 0; s < SS; s++) {
                unsigned xu = ids[rr][s] * a + b;
                int x = (int)xu;
                long long m = (long long)x % (long long)PRIME;
                if (m < 0) m += (long long)PRIME;
                mn = min(mn, (unsigned)m);
            }
            res[rr] = mn;
        }
    }
    unsigned* dst = g_sigT + ((size_t)z * KH + k) * LL + l0;
    *(uint4*)dst       = make_uint4(res[0], res[1], res[2], res[3]);
    *(uint4*)(dst + 4) = make_uint4(res[4], res[5], res[6], res[7]);
}

// ---------------- hash join: bounded probing, divergence-free probe ----------
__global__ __launch_bounds__(512) void hashjoin_kernel() {
    __shared__ unsigned tval[TBL];
    __shared__ unsigned short trow2[TBL];
    __shared__ unsigned ovf_v[MAXOVF];
    __shared__ unsigned short ovf_r[MAXOVF];
    __shared__ int n_ovf;
    int k = blockIdx.x, b = blockIdx.y;
    int tid = threadIdx.x;
    if (tid == 0) n_ovf = 0;
    #pragma unroll
    for (int i = tid; i < TBL; i += 512) tval[i] = EMPTYV;
    __syncthreads();
    const unsigned* SK = g_sigT + ((size_t)((BZ + b) * KH + k)) * LL;
    const unsigned* SQ = g_sigT + ((size_t)(b * KH + k)) * LL;

    for (int j = tid; j < LL; j += 512) {
        unsigned v = SK[j];
        unsigned x = v; x ^= x >> 16; x *= 0x85ebca6bu; x ^= x >> 13;
        int h = (int)(x & (TMASK & ~3));
        bool done = false;
        #pragma unroll
        for (int p = 0; p < 8; p++) {
            if (!done) {
                int s = (h + p) & TMASK;
                unsigned old = atomicCAS(&tval[s], EMPTYV, v);
                if (old == EMPTYV) { trow2[s] = (unsigned short)j; done = true; }
            }
        }
        if (!done) {
            int pos = atomicAdd(&n_ovf, 1);
            ovf_v[pos] = v; ovf_r[pos] = (unsigned short)j;
        }
    }
    __syncthreads();
    int nov = n_ovf;

    for (int i = tid; i < LL; i += 512) {
        unsigned v = SQ[i];
        unsigned x = v; x ^= x >> 16; x *= 0x85ebca6bu; x ^= x >> 13;
        int h = (int)(x & (TMASK & ~3));
        uint4 t0 = *(const uint4*)&tval[h];
        uint4 t1 = *(const uint4*)&tval[(h + 4) & TMASK];
        unsigned tv[8] = {t0.x, t0.y, t0.z, t0.w, t1.x, t1.y, t1.z, t1.w};
        #pragma unroll
        for (int p = 0; p < 8; p++) {
            if (tv[p] == v) {
                int s = (h + p) & TMASK;
                int row = b * LL + i;
                int pos = atomicAdd(&g_evc[row], 1);
                if (pos < EVCAP) g_evj[(size_t)row * EVCAP + pos] = trow2[s];
            }
        }
        for (int o = 0; o < nov; o++) {
            if (ovf_v[o] == v) {
                int row = b * LL + i;
                int pos = atomicAdd(&g_evc[row], 1);
                if (pos < EVCAP) g_evj[(size_t)row * EVCAP + pos] = ovf_r[o];
            }
        }
    }
}

// ---------------- per-row: sort-free dedup via count-and-rank ----------------
// warp per row; canonical (rank = position in sorted-distinct-j order)
__global__ __launch_bounds__(256) void build_sparse_kernel() {
    __shared__ int           ev[8][EVCAP];
    __shared__ float         wv[8][EVCAP];
    __shared__ unsigned char fl[8][EVCAP];
    int w = threadIdx.x >> 5;
    int lane = threadIdx.x & 31;
    int row = blockIdx.x * 8 + w;
    int n = g_evc[row];
    if (n > EVCAP) n = EVCAP;
    int* e = ev[w];
    float* wvv = wv[w];
    unsigned char* f = fl[w];
    for (int p = lane; p < n; p += 32)
        e[p] = g_evj[(size_t)row * EVCAP + p];
    __syncwarp();
    // pass 1: first-occurrence flags
    for (int p = lane; p < n; p += 32) {
        int jp = e[p];
        int fr = 1;
        for (int q = 0; q < p; q++) fr &= (e[q] != jp);
        f[p] = (unsigned char)fr;
    }
    __syncwarp();
    // pass 2: multiplicity + rank for first occurrences
    int* oi = g_nzi + (size_t)row * EVCAP;
    float* ow = g_nzw + (size_t)row * EVCAP;
    float lut0 = g_lut[0];
    int myfirst = 0;
    for (int p = lane; p < n; p += 32) {
        if (f[p]) {
            int jp = e[p];
            int m = 0, rank = 0;
            for (int q = 0; q < n; q++) {
                m += (e[q] == jp);
                rank += (f[q] && e[q] < jp);
            }
            float wgt = g_lut[m] - lut0;
            oi[rank] = jp;
            ow[rank] = wgt;
            wvv[rank] = wgt;
            myfirst++;
        }
    }
    #pragma unroll
    for (int o = 16; o; o >>= 1) myfirst += __shfl_xor_sync(0xffffffffu, myfirst, o);
    __syncwarp();
    // canonical denominator: sum weights in rank order
    float corr = 0.f;
    for (int r = lane; r < myfirst; r += 32) corr += wvv[r];
    #pragma unroll
    for (int o = 16; o; o >>= 1) corr += __shfl_xor_sync(0xffffffffu, corr, o);
    if (lane == 0) {
        g_nzc[row] = myfirst;
        g_rowinv[row] = 1.0f / (1024.0f * lut0 + corr);
    }
}

// ---------------- M2 GEMM (NN), splitK=4 ----------------
__global__ __launch_bounds__(256) void gemm_M2_kernel(const float* __restrict__ Wo,
                                                      const float* __restrict__ Wv) {
    __shared__ float As[16][68];
    __shared__ float Bs[16][68];
    int tid = threadIdx.x;
    int mi = tid & 15, ni = tid >> 4;
    int i0 = blockIdx.x * 64, j0 = blockIdx.y * 64;
    int kz = blockIdx.z;
    float acc[4][4] = {};
    for (int k0 = kz * 128; k0 < kz * 128 + 128; k0 += 16) {
        {
            int ar = tid >> 2, ac = tid & 3;
            float4 v = *(const float4*)&Wo[(size_t)(i0 + ar) * EE + k0 + ac * 4];
            As[ac * 4 + 0][ar] = v.x; As[ac * 4 + 1][ar] = v.y;
            As[ac * 4 + 2][ar] = v.z; As[ac * 4 + 3][ar] = v.w;
        }
        {
            int kk = tid >> 4, jseg = tid & 15;
            *(float4*)&Bs[kk][jseg * 4] =
                *(const float4*)&Wv[(size_t)(k0 + kk) * EE + j0 + jseg * 4];
        }
        __syncthreads();
        #pragma unroll
        for (int k = 0; k < 16; k++) {
            float4 a4 = *(float4*)&As[k][mi * 4];
            float4 b4 = *(float4*)&Bs[k][ni * 4];
            float a[4] = {a4.x, a4.y, a4.z, a4.w};
            float bb[4] = {b4.x, b4.y, b4.z, b4.w};
            #pragma unroll
            for (int r = 0; r < 4; r++)
                #pragma unroll
                for (int c = 0; c < 4; c++)
                    acc[r][c] += a[r] * bb[c];
        }
        __syncthreads();
    }
    float* outp = g_Mpart + (size_t)kz * EE * EE;
    #pragma unroll
    for (int r = 0; r < 4; r++) {
        float4 o = make_float4(acc[r][0], acc[r][1], acc[r][2], acc[r][3]);
        *(float4*)&outp[(size_t)(i0 + mi * 4 + r) * EE + j0 + ni * 4] = o;
    }
}

__global__ void reduceM_kernel() {
    int idx = blockIdx.x * 256 + threadIdx.x;
    g_M[idx] = g_Mpart[idx] + g_Mpart[idx + EE * EE]
             + g_Mpart[idx + 2 * EE * EE] + g_Mpart[idx + 3 * EE * EE];
}

// ---------------- u GEMM (f32x2, R5 measured-best config) ---------------------
__global__ __launch_bounds__(256) void gemm_u_kernel(const float* __restrict__ value) {
    __shared__ float As[16][132];
    __shared__ float Bs[16][132];
    int tid = threadIdx.x;
    int mi = tid & 15, ni = tid >> 4;
    int rt = blockIdx.x;
    int b = rt >> 3;
    int i0 = (rt & 7) * 128;
    int j0 = blockIdx.y * 128;
    const float* A = value + ((size_t)(b * LL) + i0) * EE;
    const float* B = g_M + (size_t)j0 * EE;

    unsigned long long acc[2][2][2][4];
    #pragma unroll
    for (int rh = 0; rh < 2; rh++)
        #pragma unroll
        for (int rp = 0; rp < 2; rp++)
            #pragma unroll
            for (int ch = 0; ch < 2; ch++)
                #pragma unroll
                for (int cc = 0; cc < 4; cc++)
                    acc[rh][rp][ch][cc] = 0ULL;

    int sr = tid >> 2, sc = tid & 3;
    float4 pa0, pa1, pb0, pb1;
    pa0 = *(const float4*)(A + (size_t)sr * EE + sc * 4);
    pa1 = *(const float4*)(A + (size_t)(sr + 64) * EE + sc * 4);
    pb0 = *(const float4*)(B + (size_t)sr * EE + sc * 4);
    pb1 = *(const float4*)(B + (size_t)(sr + 64) * EE + sc * 4);

    for (int t = 0; t < 32; t++) {
        As[sc * 4 + 0][sr] = pa0.x; As[sc * 4 + 1][sr] = pa0.y;
        As[sc * 4 + 2][sr] = pa0.z; As[sc * 4 + 3][sr] = pa0.w;
        As[sc * 4 + 0][sr + 64] = pa1.x; As[sc * 4 + 1][sr + 64] = pa1.y;
        As[sc * 4 + 2][sr + 64] = pa1.z; As[sc * 4 + 3][sr + 64] = pa1.w;
        Bs[sc * 4 + 0][sr] = pb0.x; Bs[sc * 4 + 1][sr] = pb0.y;
        Bs[sc * 4 + 2][sr] = pb0.z; Bs[sc * 4 + 3][sr] = pb0.w;
        Bs[sc * 4 + 0][sr + 64] = pb1.x; Bs[sc * 4 + 1][sr + 64] = pb1.y;
        Bs[sc * 4 + 2][sr + 64] = pb1.z; Bs[sc * 4 + 3][sr + 64] = pb1.w;
        __syncthreads();
        if (t < 31) {
            int k0 = (t + 1) * 16;
            pa0 = *(const float4*)(A + (size_t)sr * EE + k0 + sc * 4);
            pa1 = *(const float4*)(A + (size_t)(sr + 64) * EE + k0 + sc * 4);
            pb0 = *(const float4*)(B + (size_t)sr * EE + k0 + sc * 4);
            pb1 = *(const float4*)(B + (size_t)(sr + 64) * EE + k0 + sc * 4);
        }
        #pragma unroll
        for (int kk = 0; kk < 16; kk++) {
            float4 a0 = *(float4*)&As[kk][mi * 4];
            float4 a1 = *(float4*)&As[kk][64 + mi * 4];
            float4 b0 = *(float4*)&Bs[kk][ni * 4];
            float4 b1 = *(float4*)&Bs[kk][64 + ni * 4];
            unsigned long long pa[2][2], pb[2][4];
            pa[0][0] = pk_ab(a0.x, a0.y); pa[0][1] = pk_ab(a0.z, a0.w);
            pa[1][0] = pk_ab(a1.x, a1.y); pa[1][1] = pk_ab(a1.z, a1.w);
            pb[0][0] = pk_dup(b0.x); pb[0][1] = pk_dup(b0.y);
            pb[0][2] = pk_dup(b0.z); pb[0][3] = pk_dup(b0.w);
            pb[1][0] = pk_dup(b1.x); pb[1][1] = pk_dup(b1.y);
            pb[1][2] = pk_dup(b1.z); pb[1][3] = pk_dup(b1.w);
            #pragma unroll
            for (int rh = 0; rh < 2; rh++)
                #pragma unroll
                for (int rp = 0; rp < 2; rp++)
                    #pragma unroll
                    for (int ch = 0; ch < 2; ch++)
                        #pragma unroll
                        for (int cc = 0; cc < 4; cc++)
                            ffma2(acc[rh][rp][ch][cc], pa[rh][rp], pb[ch][cc]);
        }
        __syncthreads();
    }

    #pragma unroll
    for (int rh = 0; rh < 2; rh++)
        #pragma unroll
        for (int rp = 0; rp < 2; rp++)
            #pragma unroll
            for (int h = 0; h < 2; h++) {
                int row = i0 + rh * 64 + mi * 4 + 2 * rp + h;
                float* orow = g_u + ((size_t)(b * LL) + row) * EE + j0;
                #pragma unroll
                for (int ch = 0; ch < 2; ch++) {
                    float2 v0 = up2(acc[rh][rp][ch][0]);
                    float2 v1 = up2(acc[rh][rp][ch][1]);
                    float2 v2 = up2(acc[rh][rp][ch][2]);
                    float2 v3 = up2(acc[rh][rp][ch][3]);
                    float4 o = h ? make_float4(v0.y, v1.y, v2.y, v3.y)
                                 : make_float4(v0.x, v1.x, v2.x, v3.x);
                    *(float4*)(orow + ch * 64 + ni * 4) = o;
                }
            }
}

// ---------------- dense-term chain ----------------
__global__ __launch_bounds__(256) void vsum1_kernel(const float* __restrict__ value) {
    int b = blockIdx.y, lc = blockIdx.x;
    const float* vp = value + ((size_t)b * LL + lc * 64) * EE;
    int e = threadIdx.x;
    float a0 = 0.f, a1 = 0.f;
    for (int r = 0; r < 64; r++) {
        a0 += vp[(size_t)r * EE + e];
        a1 += vp[(size_t)r * EE + e + 256];
    }
    g_vsumP[(size_t)(b * 16 + lc) * EE + e] = a0;
    g_vsumP[(size_t)(b * 16 + lc) * EE + e + 256] = a1;
}
// fused vsum2+usum
__global__ __launch_bounds__(256) void usum_kernel() {
    __shared__ float vs[EE];
    int b = blockIdx.y;
    int t = threadIdx.x;
    {
        float s0 = 0.f, s1 = 0.f;
        for (int c = 0; c < 16; c++) {
            s0 += g_vsumP[(size_t)(b * 16 + c) * EE + t];
            s1 += g_vsumP[(size_t)(b * 16 + c) * EE + t + 256];
        }
        vs[t] = s0;
        vs[t + 256] = s1;
    }
    __syncthreads();
    int e2 = blockIdx.x * 8 + (t >> 5);
    int lane = t & 31;
    const float* mr = g_M + (size_t)e2 * EE;
    float s = 0.f;
    #pragma unroll 4
    for (int i = lane; i < EE; i += 32) s += mr[i] * vs[i];
    #pragma unroll
    for (int o = 16; o; o >>= 1) s += __shfl_xor_sync(0xffffffffu, s, o);
    if (lane == 0) g_usum[b * EE + e2] = s;
}

// ---------------- output ----------------
__global__ __launch_bounds__(128) void out_kernel(float* __restrict__ out) {
    int row = blockIdx.x;
    int b = row >> 10;
    int e4 = threadIdx.x;
    float lut0 = g_lut[0];
    float4 us = ((const float4*)g_usum)[b * 128 + e4];
    float4 acc = make_float4(us.x * lut0, us.y * lut0, us.z * lut0, us.w * lut0);
    int n = g_nzc[row];
    const int* oi = g_nzi + (size_t)row * EVCAP;
    const float* ow = g_nzw + (size_t)row * EVCAP;
    const float4* ub = (const float4*)g_u + (size_t)b * LL * 128;
    for (int t = 0; t < n; t++) {
        int j = oi[t];
        float w = ow[t];
        float4 u4 = ub[(size_t)j * 128 + e4];
        acc.x += w * u4.x; acc.y += w * u4.y;
        acc.z += w * u4.z; acc.w += w * u4.w;
    }
    float inv = g_rowinv[row];
    float4 cc = ((const float4*)g_cvec)[e4];
    float4 o = make_float4(acc.x * inv + cc.x, acc.y * inv + cc.y,
                           acc.z * inv + cc.z, acc.w * inv + cc.w);
    ((float4*)out)[(size_t)row * 128 + e4] = o;
}

// ---------------- launch: serial (measured-best scheduling) ----------------
extern "C" void kernel_launch(void* const* d_in, const int* in_sizes, int n_in,
                              void* d_out, int out_size) {
    const float* value = (const float*)d_in[2];
    const void*  tsq   = d_in[3];
    const void*  tsk   = d_in[4];
    const void*  ha    = d_in[5];
    const void*  hb    = d_in[6];
    const float* Wv    = (const float*)d_in[11];
    const float* bv    = (const float*)d_in[12];
    const float* Wo    = (const float*)d_in[13];
    const float* bo    = (const float*)d_in[14];
    float* out = (float*)d_out;

    init_kernel<<<81, 256>>>(ha, Wo, bv, bo);                           // 0
    sketch_kernel<<<2 * BZ * LL / 8, 128>>>(tsq, tsk, ha, hb);          // 1
    hashjoin_kernel<<<dim3(KH, BZ), 512>>>();                           // 2
    build_sparse_kernel<<<BZ * LL / 8, 256>>>();                        // 3 <- profiled
    gemm_M2_kernel<<<dim3(8, 8, 4), 256>>>(Wo, Wv);                     // 4
    reduceM_kernel<<<EE * EE / 256, 256>>>();                           // 5
    gemm_u_kernel<<<dim3(BZ * LL / 128, EE / 128), 256>>>(value);       // 6
    vsum1_kernel<<<dim3(16, BZ), 256>>>(value);                         // 7
    usum_kernel<<<dim3(EE / 8, BZ), 256>>>();                           // 8
    out_kernel<<<BZ * LL, 128>>>(out);                                  // 9
}

// round 17
// speedup vs baseline: 1.2768x; 1.0026x over previous
#include <cuda_runtime.h>
#include <cuda_bf16.h>
#include <stdint.h>

#define BZ 4
#define LL 1024
#define SS 8
#define KH 128
#define EE 512
#define PRIME 2147483647u
#define EMPTYV 0xffffffffu
#define EVCAP 256
#define TBL 4096
#define TMASK 4095
#define MAXOVF 1024

// ---------------- device scratch ----------------
__device__ __align__(16) unsigned int  g_sigT[2 * BZ * KH * LL];   // [z][k][l]
__device__ float         g_lut[129];
__device__ int           g_is64;
__device__ __align__(16) float         g_Mpart[4 * EE * EE];
__device__ __align__(16) float         g_M[EE * EE];             // M2 [e2][e1] fp32
__device__ __align__(16) __nv_bfloat16 g_ubf[BZ * LL * EE];      // u bf16 [b][r][e2]
__device__ __align__(16) float         g_vsumP[16 * BZ * EE];
__device__ __align__(16) float         g_usum[BZ * EE];
__device__ __align__(16) float         g_cvec[EE];
__device__ float         g_rowinv[BZ * LL];
__device__ int           g_evc[BZ * LL];
__device__ __align__(16) int           g_evj[BZ * LL * EVCAP];
__device__ int           g_nzc[BZ * LL];
__device__ __align__(16) int           g_nzi[BZ * LL * EVCAP];
__device__ __align__(16) float         g_nzw[BZ * LL * EVCAP];

// ---------------- f32x2 helpers ----------------
__device__ __forceinline__ unsigned long long pk_dup(float x) {
    unsigned long long d;
    unsigned u = __float_as_uint(x);
    asm("mov.b64 %0, {%1, %1};" : "=l"(d) : "r"(u));
    return d;
}
__device__ __forceinline__ unsigned long long pk_ab(float x, float y) {
    unsigned long long d;
    asm("mov.b64 %0, {%1, %2};" : "=l"(d) : "r"(__float_as_uint(x)), "r"(__float_as_uint(y)));
    return d;
}
__device__ __forceinline__ void ffma2(unsigned long long& d, unsigned long long a,
                                      unsigned long long b) {
    asm("fma.rn.f32x2 %0, %1, %2, %0;" : "+l"(d) : "l"(a), "l"(b));
}
__device__ __forceinline__ float2 up2(unsigned long long d) {
    unsigned lo, hi;
    asm("mov.b64 {%0, %1}, %2;" : "=r"(lo), "=r"(hi) : "l"(d));
    return make_float2(__uint_as_float(lo), __uint_as_float(hi));
}

// ---------------- init: dtype detect + LUT + zero evc + cvec ----------------
__global__ __launch_bounds__(256) void init_kernel(const void* ha,
                                                   const float* __restrict__ Wo,
                                                   const float* __restrict__ bv,
                                                   const float* __restrict__ bo) {
    int bid = blockIdx.x;
    if (bid == 0) {
        int t = threadIdx.x;
        if (t == 0) {
            const int* p = (const int*)ha;
            int is64 = 1;
            for (int i = 0; i < 16; i++)
                if (p[2 * i + 1] != 0) is64 = 0;
            g_is64 = is64;
        }
        if (t < 129) {
            float j = (float)t / 128.0f;
            float delta = 16.0f * (1.0f - j) / (1.0f + j);
            float s = expf(-0.3f * delta);
            g_lut[t] = expf(s);
        }
        return;
    }
    if (bid <= 16) {
        g_evc[(bid - 1) * 256 + threadIdx.x] = 0;
        return;
    }
    int e2 = (bid - 17) * 8 + (threadIdx.x >> 5);
    int lane = threadIdx.x & 31;
    const float* wr = Wo + (size_t)e2 * EE;
    float s = 0.f;
    for (int i = lane; i < EE; i += 32) s += wr[i] * bv[i];
    #pragma unroll
    for (int o = 16; o; o >>= 1) s += __shfl_xor_sync(0xffffffffu, s, o);
    if (lane == 0) g_cvec[e2] = s + bo[e2];
}

// ---------------- MinHash sketches, fused transpose write ----------------
__global__ __launch_bounds__(128) void sketch_kernel(const void* tsq, const void* tsk,
                                                     const void* ha, const void* hb) {
    __shared__ unsigned ids[8][SS];
    int blk = blockIdx.x;
    int row0 = blk * 8;
    int qk = row0 >> 12;
    int r0 = row0 & (BZ * LL - 1);
    int b_ = r0 >> 10, l0 = r0 & (LL - 1);
    int z = qk * BZ + b_;
    int k = threadIdx.x;
    int is64 = g_is64;
    const void* tsel = qk ? tsk : tsq;
    if (k < 64) {
        int rr = k >> 3, s = k & 7;
        ids[rr][s] = is64 ? ((const unsigned*)tsel)[((r0 + rr) * SS + s) * 2]
                          : ((const unsigned*)tsel)[(r0 + rr) * SS + s];
    }
    __syncthreads();
    unsigned res[8];
    if (is64) {
        unsigned a = ((const unsigned*)ha)[2 * k];
        unsigned b = ((const unsigned*)hb)[2 * k];
        #pragma unroll
        for (int rr = 0; rr < 8; rr++) {
            unsigned mn = 0xffffffffu;
            #pragma unroll
            for (int s = 0; s < SS; s++) {
                unsigned long long x = (unsigned long long)ids[rr][s] * a + b;
                unsigned t = (unsigned)(x >> 31) + ((unsigned)x & 0x7fffffffu);
                t = min(t, t - PRIME);
                mn = min(mn, t);
            }
            res[rr] = mn;
        }
    } else {
        unsigned a = ((const unsigned*)ha)[k];
        unsigned b = ((const unsigned*)hb)[k];
        #pragma unroll
        for (int rr = 0; rr < 8; rr++) {
            unsigned mn = 0xffffffffu;
            #pragma unroll
            for (int s = 0; s < SS; s++) {
                unsigned xu = ids[rr][s] * a + b;
                int x = (int)xu;
                long long m = (long long)x % (long long)PRIME;
                if (m < 0) m += (long long)PRIME;
                mn = min(mn, (unsigned)m);
            }
            res[rr] = mn;
        }
    }
    unsigned* dst = g_sigT + ((size_t)z * KH + k) * LL + l0;
    *(uint4*)dst       = make_uint4(res[0], res[1], res[2], res[3]);
    *(uint4*)(dst + 4) = make_uint4(res[4], res[5], res[6], res[7]);
}

// ---------------- hash join: bounded probing, divergence-free probe ----------
__global__ __launch_bounds__(512) void hashjoin_kernel() {
    __shared__ unsigned tval[TBL];
    __shared__ unsigned short trow2[TBL];
    __shared__ unsigned ovf_v[MAXOVF];
    __shared__ unsigned short ovf_r[MAXOVF];
    __shared__ int n_ovf;
    int k = blockIdx.x, b = blockIdx.y;
    int tid = threadIdx.x;
    if (tid == 0) n_ovf = 0;
    #pragma unroll
    for (int i = tid; i < TBL; i += 512) tval[i] = EMPTYV;
    __syncthreads();
    const unsigned* SK = g_sigT + ((size_t)((BZ + b) * KH + k)) * LL;
    const unsigned* SQ = g_sigT + ((size_t)(b * KH + k)) * LL;

    for (int j = tid; j < LL; j += 512) {
        unsigned v = SK[j];
        unsigned x = v; x ^= x >> 16; x *= 0x85ebca6bu; x ^= x >> 13;
        int h = (int)(x & (TMASK & ~3));
        bool done = false;
        #pragma unroll
        for (int p = 0; p < 8; p++) {
            if (!done) {
                int s = (h + p) & TMASK;
                unsigned old = atomicCAS(&tval[s], EMPTYV, v);
                if (old == EMPTYV) { trow2[s] = (unsigned short)j; done = true; }
            }
        }
        if (!done) {
            int pos = atomicAdd(&n_ovf, 1);
            ovf_v[pos] = v; ovf_r[pos] = (unsigned short)j;
        }
    }
    __syncthreads();
    int nov = n_ovf;

    for (int i = tid; i < LL; i += 512) {
        unsigned v = SQ[i];
        unsigned x = v; x ^= x >> 16; x *= 0x85ebca6bu; x ^= x >> 13;
        int h = (int)(x & (TMASK & ~3));
        uint4 t0 = *(const uint4*)&tval[h];
        uint4 t1 = *(const uint4*)&tval[(h + 4) & TMASK];
        unsigned tv[8] = {t0.x, t0.y, t0.z, t0.w, t1.x, t1.y, t1.z, t1.w};
        #pragma unroll
        for (int p = 0; p < 8; p++) {
            if (tv[p] == v) {
                int s = (h + p) & TMASK;
                int row = b * LL + i;
                int pos = atomicAdd(&g_evc[row], 1);
                if (pos < EVCAP) g_evj[(size_t)row * EVCAP + pos] = trow2[s];
            }
        }
        for (int o = 0; o < nov; o++) {
            if (ovf_v[o] == v) {
                int row = b * LL + i;
                int pos = atomicAdd(&g_evc[row], 1);
                if (pos < EVCAP) g_evj[(size_t)row * EVCAP + pos] = ovf_r[o];
            }
        }
    }
}

// ---------------- per-row: sort-free dedup via count-and-rank ----------------
__global__ __launch_bounds__(256) void build_sparse_kernel() {
    __shared__ int           ev[8][EVCAP];
    __shared__ float         wv[8][EVCAP];
    __shared__ unsigned char fl[8][EVCAP];
    int w = threadIdx.x >> 5;
    int lane = threadIdx.x & 31;
    int row = blockIdx.x * 8 + w;
    int n = g_evc[row];
    if (n > EVCAP) n = EVCAP;
    int* e = ev[w];
    float* wvv = wv[w];
    unsigned char* f = fl[w];
    for (int p = lane; p < n; p += 32)
        e[p] = g_evj[(size_t)row * EVCAP + p];
    __syncwarp();
    for (int p = lane; p < n; p += 32) {
        int jp = e[p];
        int fr = 1;
        for (int q = 0; q < p; q++) fr &= (e[q] != jp);
        f[p] = (unsigned char)fr;
    }
    __syncwarp();
    int* oi = g_nzi + (size_t)row * EVCAP;
    float* ow = g_nzw + (size_t)row * EVCAP;
    float lut0 = g_lut[0];
    int myfirst = 0;
    for (int p = lane; p < n; p += 32) {
        if (f[p]) {
            int jp = e[p];
            int m = 0, rank = 0;
            for (int q = 0; q < n; q++) {
                m += (e[q] == jp);
                rank += (f[q] && e[q] < jp);
            }
            float wgt = g_lut[m] - lut0;
            oi[rank] = jp;
            ow[rank] = wgt;
            wvv[rank] = wgt;
            myfirst++;
        }
    }
    #pragma unroll
    for (int o = 16; o; o >>= 1) myfirst += __shfl_xor_sync(0xffffffffu, myfirst, o);
    __syncwarp();
    float corr = 0.f;
    for (int r = lane; r < myfirst; r += 32) corr += wvv[r];
    #pragma unroll
    for (int o = 16; o; o >>= 1) corr += __shfl_xor_sync(0xffffffffu, corr, o);
    if (lane == 0) {
        g_nzc[row] = myfirst;
        g_rowinv[row] = 1.0f / (1024.0f * lut0 + corr);
    }
}

// ---------------- M2 GEMM (NN), splitK=4 ----------------
__global__ __launch_bounds__(256) void gemm_M2_kernel(const float* __restrict__ Wo,
                                                      const float* __restrict__ Wv) {
    __shared__ float As[16][68];
    __shared__ float Bs[16][68];
    int tid = threadIdx.x;
    int mi = tid & 15, ni = tid >> 4;
    int i0 = blockIdx.x * 64, j0 = blockIdx.y * 64;
    int kz = blockIdx.z;
    float acc[4][4] = {};
    for (int k0 = kz * 128; k0 < kz * 128 + 128; k0 += 16) {
        {
            int ar = tid >> 2, ac = tid & 3;
            float4 v = *(const float4*)&Wo[(size_t)(i0 + ar) * EE + k0 + ac * 4];
            As[ac * 4 + 0][ar] = v.x; As[ac * 4 + 1][ar] = v.y;
            As[ac * 4 + 2][ar] = v.z; As[ac * 4 + 3][ar] = v.w;
        }
        {
            int kk = tid >> 4, jseg = tid & 15;
            *(float4*)&Bs[kk][jseg * 4] =
                *(const float4*)&Wv[(size_t)(k0 + kk) * EE + j0 + jseg * 4];
        }
        __syncthreads();
        #pragma unroll
        for (int k = 0; k < 16; k++) {
            float4 a4 = *(float4*)&As[k][mi * 4];
            float4 b4 = *(float4*)&Bs[k][ni * 4];
            float a[4] = {a4.x, a4.y, a4.z, a4.w};
            float bb[4] = {b4.x, b4.y, b4.z, b4.w};
            #pragma unroll
            for (int r = 0; r < 4; r++)
                #pragma unroll
                for (int c = 0; c < 4; c++)
                    acc[r][c] += a[r] * bb[c];
        }
        __syncthreads();
    }
    float* outp = g_Mpart + (size_t)kz * EE * EE;
    #pragma unroll
    for (int r = 0; r < 4; r++) {
        float4 o = make_float4(acc[r][0], acc[r][1], acc[r][2], acc[r][3]);
        *(float4*)&outp[(size_t)(i0 + mi * 4 + r) * EE + j0 + ni * 4] = o;
    }
}

__global__ void reduceM_kernel() {
    int idx = blockIdx.x * 256 + threadIdx.x;
    g_M[idx] = g_Mpart[idx] + g_Mpart[idx + EE * EE]
             + g_Mpart[idx + 2 * EE * EE] + g_Mpart[idx + 3 * EE * EE];
}

// ---------------- u GEMM (f32x2, R5 config; fp32 accum, bf16 store) -----------
__global__ __launch_bounds__(256) void gemm_u_kernel(const float* __restrict__ value) {
    __shared__ float As[16][132];
    __shared__ float Bs[16][132];
    int tid = threadIdx.x;
    int mi = tid & 15, ni = tid >> 4;
    int rt = blockIdx.x;
    int b = rt >> 3;
    int i0 = (rt & 7) * 128;
    int j0 = blockIdx.y * 128;
    const float* A = value + ((size_t)(b * LL) + i0) * EE;
    const float* B = g_M + (size_t)j0 * EE;

    unsigned long long acc[2][2][2][4];
    #pragma unroll
    for (int rh = 0; rh < 2; rh++)
        #pragma unroll
        for (int rp = 0; rp < 2; rp++)
            #pragma unroll
            for (int ch = 0; ch < 2; ch++)
                #pragma unroll
                for (int cc = 0; cc < 4; cc++)
                    acc[rh][rp][ch][cc] = 0ULL;

    int sr = tid >> 2, sc = tid & 3;
    float4 pa0, pa1, pb0, pb1;
    pa0 = *(const float4*)(A + (size_t)sr * EE + sc * 4);
    pa1 = *(const float4*)(A + (size_t)(sr + 64) * EE + sc * 4);
    pb0 = *(const float4*)(B + (size_t)sr * EE + sc * 4);
    pb1 = *(const float4*)(B + (size_t)(sr + 64) * EE + sc * 4);

    for (int t = 0; t < 32; t++) {
        As[sc * 4 + 0][sr] = pa0.x; As[sc * 4 + 1][sr] = pa0.y;
        As[sc * 4 + 2][sr] = pa0.z; As[sc * 4 + 3][sr] = pa0.w;
        As[sc * 4 + 0][sr + 64] = pa1.x; As[sc * 4 + 1][sr + 64] = pa1.y;
        As[sc * 4 + 2][sr + 64] = pa1.z; As[sc * 4 + 3][sr + 64] = pa1.w;
        Bs[sc * 4 + 0][sr] = pb0.x; Bs[sc * 4 + 1][sr] = pb0.y;
        Bs[sc * 4 + 2][sr] = pb0.z; Bs[sc * 4 + 3][sr] = pb0.w;
        Bs[sc * 4 + 0][sr + 64] = pb1.x; Bs[sc * 4 + 1][sr + 64] = pb1.y;
        Bs[sc * 4 + 2][sr + 64] = pb1.z; Bs[sc * 4 + 3][sr + 64] = pb1.w;
        __syncthreads();
        if (t < 31) {
            int k0 = (t + 1) * 16;
            pa0 = *(const float4*)(A + (size_t)sr * EE + k0 + sc * 4);
            pa1 = *(const float4*)(A + (size_t)(sr + 64) * EE + k0 + sc * 4);
            pb0 = *(const float4*)(B + (size_t)sr * EE + k0 + sc * 4);
            pb1 = *(const float4*)(B + (size_t)(sr + 64) * EE + k0 + sc * 4);
        }
        #pragma unroll
        for (int kk = 0; kk < 16; kk++) {
            float4 a0 = *(float4*)&As[kk][mi * 4];
            float4 a1 = *(float4*)&As[kk][64 + mi * 4];
            float4 b0 = *(float4*)&Bs[kk][ni * 4];
            float4 b1 = *(float4*)&Bs[kk][64 + ni * 4];
            unsigned long long pa[2][2], pb[2][4];
            pa[0][0] = pk_ab(a0.x, a0.y); pa[0][1] = pk_ab(a0.z, a0.w);
            pa[1][0] = pk_ab(a1.x, a1.y); pa[1][1] = pk_ab(a1.z, a1.w);
            pb[0][0] = pk_dup(b0.x); pb[0][1] = pk_dup(b0.y);
            pb[0][2] = pk_dup(b0.z); pb[0][3] = pk_dup(b0.w);
            pb[1][0] = pk_dup(b1.x); pb[1][1] = pk_dup(b1.y);
            pb[1][2] = pk_dup(b1.z); pb[1][3] = pk_dup(b1.w);
            #pragma unroll
            for (int rh = 0; rh < 2; rh++)
                #pragma unroll
                for (int rp = 0; rp < 2; rp++)
                    #pragma unroll
                    for (int ch = 0; ch < 2; ch++)
                        #pragma unroll
                        for (int cc = 0; cc < 4; cc++)
                            ffma2(acc[rh][rp][ch][cc], pa[rh][rp], pb[ch][cc]);
        }
        __syncthreads();
    }

    // epilogue: fp32 accumulators -> bf16 store
    #pragma unroll
    for (int rh = 0; rh < 2; rh++)
        #pragma unroll
        for (int rp = 0; rp < 2; rp++)
            #pragma unroll
            for (int h = 0; h < 2; h++) {
                int row = i0 + rh * 64 + mi * 4 + 2 * rp + h;
                __nv_bfloat16* orow = g_ubf + ((size_t)(b * LL) + row) * EE + j0;
                #pragma unroll
                for (int ch = 0; ch < 2; ch++) {
                    float2 v0 = up2(acc[rh][rp][ch][0]);
                    float2 v1 = up2(acc[rh][rp][ch][1]);
                    float2 v2 = up2(acc[rh][rp][ch][2]);
                    float2 v3 = up2(acc[rh][rp][ch][3]);
                    float f0 = h ? v0.y : v0.x, f1 = h ? v1.y : v1.x;
                    float f2 = h ? v2.y : v2.x, f3 = h ? v3.y : v3.x;
                    __nv_bfloat162 h0 = __floats2bfloat162_rn(f0, f1);
                    __nv_bfloat162 h1 = __floats2bfloat162_rn(f2, f3);
                    unsigned u0, u1;
                    memcpy(&u0, &h0, 4); memcpy(&u1, &h1, 4);
                    *(uint2*)(orow + ch * 64 + ni * 4) = make_uint2(u0, u1);
                }
            }
}

// ---------------- dense-term chain ----------------
__global__ __launch_bounds__(256) void vsum1_kernel(const float* __restrict__ value) {
    int b = blockIdx.y, lc = blockIdx.x;
    const float* vp = value + ((size_t)b * LL + lc * 64) * EE;
    int e = threadIdx.x;
    float a0 = 0.f, a1 = 0.f;
    for (int r = 0; r < 64; r++) {
        a0 += vp[(size_t)r * EE + e];
        a1 += vp[(size_t)r * EE + e + 256];
    }
    g_vsumP[(size_t)(b * 16 + lc) * EE + e] = a0;
    g_vsumP[(size_t)(b * 16 + lc) * EE + e + 256] = a1;
}
// fused vsum2+usum
__global__ __launch_bounds__(256) void usum_kernel() {
    __shared__ float vs[EE];
    int b = blockIdx.y;
    int t = threadIdx.x;
    {
        float s0 = 0.f, s1 = 0.f;
        for (int c = 0; c < 16; c++) {
            s0 += g_vsumP[(size_t)(b * 16 + c) * EE + t];
            s1 += g_vsumP[(size_t)(b * 16 + c) * EE + t + 256];
        }
        vs[t] = s0;
        vs[t + 256] = s1;
    }
    __syncthreads();
    int e2 = blockIdx.x * 8 + (t >> 5);
    int lane = t & 31;
    const float* mr = g_M + (size_t)e2 * EE;
    float s = 0.f;
    #pragma unroll 4
    for (int i = lane; i < EE; i += 32) s += mr[i] * vs[i];
    #pragma unroll
    for (int o = 16; o; o >>= 1) s += __shfl_xor_sync(0xffffffffu, s, o);
    if (lane == 0) g_usum[b * EE + e2] = s;
}

// ---------------- output (bf16 gathers) ----------------
__global__ __launch_bounds__(128) void out_kernel(float* __restrict__ out) {
    int row = blockIdx.x;
    int b = row >> 10;
    int e4 = threadIdx.x;              // 4 e2 per thread
    float lut0 = g_lut[0];
    float4 us = ((const float4*)g_usum)[b * 128 + e4];
    float4 acc = make_float4(us.x * lut0, us.y * lut0, us.z * lut0, us.w * lut0);
    int n = g_nzc[row];
    const int* oi = g_nzi + (size_t)row * EVCAP;
    const float* ow = g_nzw + (size_t)row * EVCAP;
    const uint2* ub = (const uint2*)g_ubf + (size_t)b * LL * 128;
    for (int t = 0; t < n; t++) {
        int j = oi[t];
        float w = ow[t];
        uint2 u2 = ub[(size_t)j * 128 + e4];
        __nv_bfloat162 h0, h1;
        memcpy(&h0, &u2.x, 4); memcpy(&h1, &u2.y, 4);
        float2 lo = __bfloat1622float2(h0);
        float2 hi = __bfloat1622float2(h1);
        acc.x += w * lo.x; acc.y += w * lo.y;
        acc.z += w * hi.x; acc.w += w * hi.y;
    }
    float inv = g_rowinv[row];
    float4 cc = ((const float4*)g_cvec)[e4];
    float4 o = make_float4(acc.x * inv + cc.x, acc.y * inv + cc.y,
                           acc.z * inv + cc.z, acc.w * inv + cc.w);
    ((float4*)out)[(size_t)row * 128 + e4] = o;
}

// ---------------- launch: serial (measured-best scheduling) ----------------
extern "C" void kernel_launch(void* const* d_in, const int* in_sizes, int n_in,
                              void* d_out, int out_size) {
    const float* value = (const float*)d_in[2];
    const void*  tsq   = d_in[3];
    const void*  tsk   = d_in[4];
    const void*  ha    = d_in[5];
    const void*  hb    = d_in[6];
    const float* Wv    = (const float*)d_in[11];
    const float* bv    = (const float*)d_in[12];
    const float* Wo    = (const float*)d_in[13];
    const float* bo    = (const float*)d_in[14];
    float* out = (float*)d_out;

    init_kernel<<<81, 256>>>(ha, Wo, bv, bo);                           // 0
    sketch_kernel<<<2 * BZ * LL / 8, 128>>>(tsq, tsk, ha, hb);          // 1
    hashjoin_kernel<<<dim3(KH, BZ), 512>>>();                           // 2
    build_sparse_kernel<<<BZ * LL / 8, 256>>>();                        // 3 <- profiled
    gemm_M2_kernel<<<dim3(8, 8, 4), 256>>>(Wo, Wv);                     // 4
    reduceM_kernel<<<EE * EE / 256, 256>>>();                           // 5
    gemm_u_kernel<<<dim3(BZ * LL / 128, EE / 128), 256>>>(value);       // 6
    vsum1_kernel<<<dim3(16, BZ), 256>>>(value);                         // 7
    usum_kernel<<<dim3(EE / 8, BZ), 256>>>();                           // 8
    out_kernel<<<BZ * LL, 128>>>(out);                                  // 9
}